// round 16
// baseline (speedup 1.0000x reference)
#include <cuda_runtime.h>
#include <cuda_bf16.h>

// RoPE, single launch, table-free, fast trig, quarter-stride streams.
// x is [BH, seq, 128] fp32. n4 = total float4s. Thread i handles the 4
// float4s {i, i+q, i+2q, i+3q} with q = n4/4 (the R5 memory shape that
// measured the best DRAM% of the session). When bh % 4 == 0, q is a multiple
// of seq*32, so all four indices share the same (s, d4): one cos/sin
// quadruple per thread, computed with exact FP32 Cody-Waite reduction +
// MUFU sin/cos under the front-batched load latency. regs ~30, occ ~80%.

#define D_MODEL   128
#define D_VEC4    32            // D_MODEL/4
#define NTHREADS  256
#define MAX_SEQ   8192

__device__ __forceinline__ float4 rope_rot(float4 v, float4 t) {
    float4 o;
    o.x = fmaf(t.x, v.x, -t.y * v.y);
    o.y = fmaf(t.y, v.x,  t.x * v.y);
    o.z = fmaf(t.z, v.z, -t.w * v.w);
    o.w = fmaf(t.w, v.z,  t.z * v.w);
    return o;
}

// Cody-Waite two-constant reduction (FMA-exact) + HW sin/cos approx on the
// reduced argument (|r| <= pi, abs err ~7e-7).
__device__ __forceinline__ void fast_sincos(float ang, float* sn, float* cs) {
    const float INV_2PI   = 0.15915494309189535f;
    const float TWO_PI_HI = 6.283185482025146484375f;   // float(2*pi)
    const float TWO_PI_LO = -1.7484556000744487e-07f;   // 2*pi - HI (dbl)
    float k = rintf(ang * INV_2PI);
    float r = fmaf(k, -TWO_PI_HI, ang);
    r       = fmaf(k, -TWO_PI_LO, r);
    __sincosf(r, sn, cs);
}

// token_positions may be serialized int64 or int32. Little-endian int64
// arrays of small positives have zero odd int32 words. Probe words are
// L1/L2-hot after the first warp touches them.
__device__ __forceinline__ bool detect_is64(const void* tok, unsigned int seq) {
    if (seq < 8) return false;
    const int* v32 = (const int*)tok;
    return (__ldg(v32 + 1) == 0 && __ldg(v32 + 3) == 0 &&
            __ldg(v32 + 5) == 0 && __ldg(v32 + 7) == 0);
}

__device__ __forceinline__ long long load_pos(const void* tok, unsigned int s,
                                              bool is64) {
    return is64 ? ((const long long*)tok)[s] : (long long)((const int*)tok)[s];
}

// ---------------------------------------------------------------------------
// Fast path: d=128, seq power of two, bh % 4 == 0, n4 % NTHREADS*4 == 0
// handled via exact grid sizing (q % NTHREADS == 0 guaranteed by launcher).
// ---------------------------------------------------------------------------
__global__ void __launch_bounds__(NTHREADS)
rope_q4(const float4* __restrict__ x, float4* __restrict__ out,
        const void* __restrict__ tok_pos,
        unsigned int smask, unsigned int q) {
    unsigned int i = blockIdx.x * NTHREADS + threadIdx.x;

    unsigned int i0 = i, i1 = i + q, i2 = i + 2u * q, i3 = i + 3u * q;

    // ---- front-batch the 4 streaming loads (independent n4/4-apart streams)
    float4 v0 = __ldcs(x + i0);
    float4 v1 = __ldcs(x + i1);
    float4 v2 = __ldcs(x + i2);
    float4 v3 = __ldcs(x + i3);

    // ---- shared (s, d4) for all four streams ----
    unsigned int d4 = i & (D_VEC4 - 1);
    unsigned int s  = (i >> 5) & smask;

    const float LOG2_THETA = 13.287712379549449f;   // log2(10000)
    const float RATIO      = 0.86596432336006535f;  // 10000^(-1/64)
    bool is64 = detect_is64(tok_pos, smask + 1u);
    float pf = (float)load_pos(tok_pos, s, is64);

    float e0   = (float)(4u * d4) * (1.0f / 128.0f);     // 2*(2*d4)/d
    float ang0 = pf * exp2f(-e0 * LOG2_THETA);
    float ang1 = ang0 * RATIO;                            // exact identity

    float4 t;
    fast_sincos(ang0, &t.y, &t.x);   // t.x=cos0, t.y=sin0
    fast_sincos(ang1, &t.w, &t.z);   // t.z=cos1, t.w=sin1

    // ---- rotate + store ----
    __stcs(out + i0, rope_rot(v0, t));
    __stcs(out + i1, rope_rot(v1, t));
    __stcs(out + i2, rope_rot(v2, t));
    __stcs(out + i3, rope_rot(v3, t));
}

// ---------------------------------------------------------------------------
// Fallback (generic shapes): table + streaming kernels (accurate sincosf;
// off the fast path, cost irrelevant).
// ---------------------------------------------------------------------------
__device__ float4 g_tab4[MAX_SEQ * (D_MODEL / 2) / 2];

__global__ void rope_build_table(const void* __restrict__ tok_pos, int seq) {
    int idx = blockIdx.x * blockDim.x + threadIdx.x;
    if (idx >= seq * (D_MODEL / 2)) return;
    int s = idx >> 6;
    int i = idx & (D_MODEL / 2 - 1);
    bool is64 = detect_is64(tok_pos, (unsigned)seq);
    long long p = load_pos(tok_pos, (unsigned)s, is64);
    const float LOG2_THETA = 13.287712379549449f;
    float e   = (float)(2 * i) * (1.0f / (float)D_MODEL);
    float ang = (float)p * exp2f(-e * LOG2_THETA);
    float sn, cs;
    sincosf(ang, &sn, &cs);
    ((float2*)g_tab4)[(size_t)s * (D_MODEL / 2) + i] = make_float2(cs, sn);
}

__global__ void __launch_bounds__(256)
rope_apply1(const float4* __restrict__ x, float4* __restrict__ out,
            unsigned int seq, unsigned int n4) {
    unsigned int i = blockIdx.x * blockDim.x + threadIdx.x;
    if (i >= n4) return;
    unsigned int r = i >> 5;
    unsigned int s = r % seq;
    float4 v = __ldcs(x + i);
    float4 t = g_tab4[s * D_VEC4 + (i & (D_VEC4 - 1))];
    __stcs(out + i, rope_rot(v, t));
}

// ---------------------------------------------------------------------------
extern "C" void kernel_launch(void* const* d_in, const int* in_sizes, int n_in,
                              void* d_out, int out_size) {
    const float* x  = (const float*)d_in[0];
    const void*  tp = d_in[1];

    unsigned int n_elem = (unsigned int)in_sizes[0];
    unsigned int seq    = (unsigned int)in_sizes[1];

    unsigned int n4 = n_elem / 4;
    unsigned int q  = n4 / 4;

    bool pow2   = seq > 0 && ((seq & (seq - 1)) == 0);
    bool fast   = false;
    if (pow2 && n_elem % (seq * D_MODEL) == 0) {
        unsigned int bh = n_elem / (seq * D_MODEL);
        // 4 streams share (s,d4) iff q is a multiple of seq*32 <=> bh%4==0;
        // exact grid requires q % NTHREADS == 0.
        fast = (bh % 4u == 0u) && (q % NTHREADS == 0u);
    }

    if (fast) {
        rope_q4<<<q / NTHREADS, NTHREADS>>>((const float4*)x, (float4*)d_out,
                                            tp, seq - 1u, q);
    } else {
        unsigned int su = seq > MAX_SEQ ? MAX_SEQ : seq;
        int total = (int)(su * (D_MODEL / 2));
        rope_build_table<<<(total + 255) / 256, 256>>>(tp, (int)su);
        rope_apply1<<<(n4 + 255) / 256, 256>>>(
            (const float4*)x, (float4*)d_out, su, n4);
    }
}